// round 10
// baseline (speedup 1.0000x reference)
#include <cuda_runtime.h>
#include <cuda_bf16.h>

#define BS   8
#define CH   256
#define TLEN 512
#define PBIN 16
#define SRAT 4
#define S2   130
#define NTILE 1024           // 32x32 transpose tiles: 16 t * 8 c * 8 b
#define NBLOCK 4096

// 4 MB transposed-input scratch: (b, t, c) layout so channel gathers coalesce.
__device__ float g_tr[BS * TLEN * CH];
__device__ int   g_done = 0;     // transpose-complete counter (self-resetting)
__device__ int   g_exit = 0;     // block-exit counter (self-resetting)

// ---------------------------------------------------------------------------
// Fused kernel: blocks 0..1023 first transpose one 32x32 tile of the input
// into g_tr, signal g_done; ALL blocks spin-wait for g_done==1024 (software
// grid barrier; transposers are within the first resident wave -> safe),
// then every block runs the R7-champion half-ROI ROIAlign body.
// Counters self-reset via g_exit so every graph replay starts clean.
// ---------------------------------------------------------------------------
__global__ __launch_bounds__(64, 24) void roialign_fused_kernel(
        const float* __restrict__ in,
        const float* __restrict__ rois,
        float4* __restrict__ out) {
    const int l = threadIdx.x;               // 0..63
    const int u = blockIdx.x;                // unit id (also tile id if < 1024)

    __shared__ union {
        float tile[32][33];                  // transpose phase
        struct {                             // roialign phase
            uint4 desc[PBIN * SRAT];
            float stage[PBIN * S2];
        } r;
    } sm;

    // ================= Phase 0: cooperative transpose =================
    if (u < NTILE) {
        const int b  = u >> 7;               // batch
        const int ct = u & 127;
        const int t0 = (ct >> 3) * 32;
        const int c0 = (ct & 7) * 32;
        const float* inb  = in   + (size_t)b * CH * TLEN;
        float*       outb = g_tr + (size_t)b * TLEN * CH;

        const int tx = l & 7;                // float4 column
        const int r  = l >> 3;               // row group (0..7)

        #pragma unroll
        for (int j = 0; j < 4; j++) {
            const int c = r + 8 * j;
            const float4 v = *(const float4*)&inb[(size_t)(c0 + c) * TLEN + (t0 + 4 * tx)];
            sm.tile[c][4 * tx + 0] = v.x;
            sm.tile[c][4 * tx + 1] = v.y;
            sm.tile[c][4 * tx + 2] = v.z;
            sm.tile[c][4 * tx + 3] = v.w;
        }
        __syncthreads();
        #pragma unroll
        for (int j = 0; j < 4; j++) {
            const int t = r + 8 * j;
            float4 w;
            w.x = sm.tile[4 * tx + 0][t];
            w.y = sm.tile[4 * tx + 1][t];
            w.z = sm.tile[4 * tx + 2][t];
            w.w = sm.tile[4 * tx + 3][t];
            *(float4*)&outb[(size_t)(t0 + t) * CH + (c0 + 4 * tx)] = w;
        }
        __threadfence();                     // release our g_tr stores (gpu scope)
        __syncthreads();
        if (l == 0) atomicAdd(&g_done, 1);
    }

    // ================= software grid barrier =================
    if (l == 0) {
        while (*(volatile int*)&g_done < NTILE) __nanosleep(100);
        __threadfence();                     // acquire
    }
    __syncthreads();

    // ================= Phase 1: ROIAlign (R7 champion body) =================
    const int half = u & 1;                  // which 128-channel half
    const int n    = u >> 1;                 // ROI index

    // ---- A: per-sample descriptors (thread i == sample i) ----
    {
        const float bf    = __ldg(&rois[n * 3 + 0]);
        const float start = __ldg(&rois[n * 3 + 1]);
        const float end   = __ldg(&rois[n * 3 + 2]);
        const float roi_len = fmaxf(end - start, 1.0f);
        const float bin     = roi_len * (1.0f / (float)PBIN);

        const int p = l >> 2;                // bin
        const int s = l & 3;                 // sample
        const float x = start + ((float)p + ((float)s + 0.5f) * 0.25f) * bin;
        const bool valid = (x >= -1.0f) && (x <= (float)TLEN);
        const float xc = fminf(fmaxf(x, 0.0f), (float)(TLEN - 1));
        const int xl = (int)floorf(xc);
        const int xh = min(xl + 1, TLEN - 1);
        const float lx = xc - (float)xl;
        const int b = (int)bf;

        uint4 d;
        d.x = (unsigned)(((b << 9) + xl) << 10);   // byte offset of row xl
        d.y = (unsigned)(((b << 9) + xh) << 10);   // byte offset of row xh
        d.z = __float_as_uint(valid ? (1.0f - lx) * 0.25f : 0.0f);
        d.w = __float_as_uint(valid ? lx * 0.25f : 0.0f);
        sm.r.desc[l] = d;
    }
    __syncthreads();

    // ---- B: one-line scalar gathers, 2 stride-64 channels/thread ----
    const char* base = (const char*)g_tr + (half * 128 + l) * 4;

    #pragma unroll 1
    for (int p = 0; p < PBIN; p++) {
        float a0 = 0.0f, a1 = 0.0f;
        #pragma unroll
        for (int s = 0; s < SRAT; s++) {
            const uint4 d = sm.r.desc[p * SRAT + s];
            const float wlo = __uint_as_float(d.z);
            const float whi = __uint_as_float(d.w);
            const float* lo = (const float*)(base + d.x);
            const float* hi = (const float*)(base + d.y);
            a0 += lo[0]  * wlo + hi[0]  * whi;   // chan c0
            a1 += lo[64] * wlo + hi[64] * whi;   // chan c0+64
        }
        float* row = &sm.r.stage[p * S2];
        row[l]      = a0;                    // bank (2p + l) % 32, conflict-free
        row[l + 64] = a1;
    }
    __syncthreads();

    // ---- C: coalesced float4 writeback (contiguous half-ROI range) ----
    float4* outn = out + (size_t)n * (CH * PBIN / 4) + half * 512;

    #pragma unroll
    for (int k = 0; k < 8; k++) {
        const int q = l + 64 * k;            // 0..511, coalesced
        const int c = q >> 2;                // channel within half (0..127)
        const int g = q & 3;                 // bin-group
        float4 v;
        v.x = sm.r.stage[(4 * g + 0) * S2 + c];
        v.y = sm.r.stage[(4 * g + 1) * S2 + c];
        v.z = sm.r.stage[(4 * g + 2) * S2 + c];
        v.w = sm.r.stage[(4 * g + 3) * S2 + c];
        outn[q] = v;
    }

    // ================= epilogue: self-reset for next graph replay ==========
    if (l == 0) {
        if (atomicAdd(&g_exit, 1) == NBLOCK - 1) {
            g_done = 0;                      // last block out resets counters
            g_exit = 0;
        }
    }
}

extern "C" void kernel_launch(void* const* d_in, const int* in_sizes, int n_in,
                              void* d_out, int out_size) {
    const float* input = (const float*)d_in[0];
    const float* rois  = (const float*)d_in[1];
    float4*      out   = (float4*)d_out;

    roialign_fused_kernel<<<NBLOCK, 64>>>(input, rois, out);
}

// round 11
// speedup vs baseline: 1.3758x; 1.3758x over previous
#include <cuda_runtime.h>
#include <cuda_bf16.h>

#define BS   8
#define CH   256
#define TLEN 512
#define PBIN 16
#define SRAT 4

// 4 MB transposed-input scratch: (b, t, c) layout so channel gathers coalesce.
__device__ float g_tr[BS * TLEN * CH];

// ---------------------------------------------------------------------------
// Kernel 1: transpose (b, ch, t) -> (b, t, ch), 32x32 tiles, float4 both ways.
// (identical to the R7 champion)
// ---------------------------------------------------------------------------
__global__ __launch_bounds__(256) void transpose_kernel(const float* __restrict__ in) {
    __shared__ float tile[32][33];
    const int b  = blockIdx.z;
    const int t0 = blockIdx.x * 32;
    const int c0 = blockIdx.y * 32;
    const int tx = threadIdx.x;          // 0..7  (float4 index)
    const int ty = threadIdx.y;          // 0..31

    const float* inb  = in   + (size_t)b * CH * TLEN;
    float*       outb = g_tr + (size_t)b * TLEN * CH;

    const float4 v = *(const float4*)&inb[(size_t)(c0 + ty) * TLEN + (t0 + 4 * tx)];
    tile[ty][4 * tx + 0] = v.x;
    tile[ty][4 * tx + 1] = v.y;
    tile[ty][4 * tx + 2] = v.z;
    tile[ty][4 * tx + 3] = v.w;
    __syncthreads();

    float4 w;
    w.x = tile[4 * tx + 0][ty];
    w.y = tile[4 * tx + 1][ty];
    w.z = tile[4 * tx + 2][ty];
    w.w = tile[4 * tx + 3][ty];
    *(float4*)&outb[(size_t)(t0 + ty) * CH + (c0 + 4 * tx)] = w;
}

// ---------------------------------------------------------------------------
// Kernel 2: R7 champion structure, but FLOAT2 gathers.
//   TWO 64-thread blocks per ROI (128 channels each), 24 blocks/SM resident.
//   Thread owns the contiguous channel pair (2l, 2l+1): each gather is one
//   LDG.64, warp footprint 256B = 2 lines -> 2 wavefronts, HALF the LDG
//   issue count of the scalar champion at identical gather bytes.
//   Fixed fully-unrolled 8-load/bin loop (ptxas front-batches). Staging
//   STS.64 conflict-free; float4 writeback unchanged from champion.
// ---------------------------------------------------------------------------
#define S2 130

__global__ __launch_bounds__(64, 24) void roialign_kernel(const float* __restrict__ rois,
                                                          float4* __restrict__ out) {
    const int half = blockIdx.x & 1;         // which 128-channel half
    const int n    = blockIdx.x >> 1;        // ROI index
    const int l    = threadIdx.x;            // 0..63

    __shared__ uint4 s_desc[PBIN * SRAT];    // 64 sample descriptors
    __shared__ float s_stage[PBIN * S2];     // [p][128 chans] stride-130 rows

    // ---- Phase A: per-sample descriptors (thread i == sample i) ----
    {
        const float bf    = __ldg(&rois[n * 3 + 0]);
        const float start = __ldg(&rois[n * 3 + 1]);
        const float end   = __ldg(&rois[n * 3 + 2]);
        const float roi_len = fmaxf(end - start, 1.0f);
        const float bin     = roi_len * (1.0f / (float)PBIN);

        const int p = l >> 2;                // bin
        const int s = l & 3;                 // sample
        const float x = start + ((float)p + ((float)s + 0.5f) * 0.25f) * bin;
        const bool valid = (x >= -1.0f) && (x <= (float)TLEN);
        const float xc = fminf(fmaxf(x, 0.0f), (float)(TLEN - 1));
        const int xl = (int)floorf(xc);
        const int xh = min(xl + 1, TLEN - 1);
        const float lx = xc - (float)xl;
        const int b = (int)bf;

        uint4 d;
        d.x = (unsigned)(((b << 9) + xl) << 10);   // byte offset of row xl
        d.y = (unsigned)(((b << 9) + xh) << 10);   // byte offset of row xh
        d.z = __float_as_uint(valid ? (1.0f - lx) * 0.25f : 0.0f);
        d.w = __float_as_uint(valid ? lx * 0.25f : 0.0f);
        s_desc[l] = d;
    }
    __syncthreads();

    // ---- Phase B: float2 gathers, contiguous channel pair per thread ----
    const char* base = (const char*)g_tr + (half * 128 + 2 * l) * 4;

    #pragma unroll 1
    for (int p = 0; p < PBIN; p++) {
        float a0 = 0.0f, a1 = 0.0f;
        #pragma unroll
        for (int s = 0; s < SRAT; s++) {
            const uint4 d = s_desc[p * SRAT + s];
            const float wlo = __uint_as_float(d.z);
            const float whi = __uint_as_float(d.w);
            const float2 lo = *(const float2*)(base + d.x);
            const float2 hi = *(const float2*)(base + d.y);
            a0 += lo.x * wlo + hi.x * whi;   // chan 2l
            a1 += lo.y * wlo + hi.y * whi;   // chan 2l+1
        }
        // STS.64 at byte offset p*520 + l*8: per half-warp banks 2l..2l+1
        // cover all 32 banks exactly once -> conflict-free.
        *(float2*)&s_stage[p * S2 + 2 * l] = make_float2(a0, a1);
    }
    __syncthreads();

    // ---- Phase C: coalesced float4 writeback (contiguous half-ROI range) ----
    float4* outn = out + (size_t)n * (CH * PBIN / 4) + half * 512;

    #pragma unroll
    for (int k = 0; k < 8; k++) {
        const int q = l + 64 * k;            // 0..511, coalesced
        const int c = q >> 2;                // channel within half (0..127)
        const int g = q & 3;                 // bin-group
        float4 v;
        v.x = s_stage[(4 * g + 0) * S2 + c];
        v.y = s_stage[(4 * g + 1) * S2 + c];
        v.z = s_stage[(4 * g + 2) * S2 + c];
        v.w = s_stage[(4 * g + 3) * S2 + c];
        outn[q] = v;
    }
}

extern "C" void kernel_launch(void* const* d_in, const int* in_sizes, int n_in,
                              void* d_out, int out_size) {
    const float* input = (const float*)d_in[0];
    const float* rois  = (const float*)d_in[1];
    float4*      out   = (float4*)d_out;

    const int N = in_sizes[1] / 3;       // 2048 ROIs

    dim3 tgrid(TLEN / 32, CH / 32, BS);  // (16, 8, 8)
    dim3 tblk(8, 32);
    transpose_kernel<<<tgrid, tblk>>>(input);

    roialign_kernel<<<N * 2, 64>>>(rois, out);
}

// round 13
// speedup vs baseline: 1.5327x; 1.1140x over previous
#include <cuda_runtime.h>
#include <cuda_fp16.h>

#define BS   8
#define CH   256
#define TLEN 512
#define PBIN 16
#define SRAT 4

// 2 MB transposed-input scratch in FP16: (b, t, c) layout.
// Halves gather bytes -> one 128B line per warp-gather instead of two.
__device__ __half2 g_tr[BS * TLEN * CH / 2];

// ---------------------------------------------------------------------------
// Kernel 1: transpose (b, ch, t) fp32 -> (b, t, ch) fp16. 32x32 tiles.
// ---------------------------------------------------------------------------
__global__ __launch_bounds__(256) void transpose_kernel(const float* __restrict__ in) {
    __shared__ float tile[32][33];
    const int b  = blockIdx.z;
    const int t0 = blockIdx.x * 32;
    const int c0 = blockIdx.y * 32;
    const int tx = threadIdx.x;          // 0..7  (float4 index)
    const int ty = threadIdx.y;          // 0..31

    const float* inb  = in   + (size_t)b * CH * TLEN;
    __half2*     outb = g_tr + (size_t)b * TLEN * (CH / 2);

    const float4 v = *(const float4*)&inb[(size_t)(c0 + ty) * TLEN + (t0 + 4 * tx)];
    tile[ty][4 * tx + 0] = v.x;
    tile[ty][4 * tx + 1] = v.y;
    tile[ty][4 * tx + 2] = v.z;
    tile[ty][4 * tx + 3] = v.w;
    __syncthreads();

    // 4 channels for token ty -> 2 half2 = one 8B store, coalesced.
    __half2 w2[2];
    w2[0] = __floats2half2_rn(tile[4 * tx + 0][ty], tile[4 * tx + 1][ty]);
    w2[1] = __floats2half2_rn(tile[4 * tx + 2][ty], tile[4 * tx + 3][ty]);
    *(uint2*)&outb[(size_t)(t0 + ty) * (CH / 2) + (c0 / 2 + 2 * tx)] = *(const uint2*)w2;
}

// ---------------------------------------------------------------------------
// Kernel 2: R11 champion structure with FP16 gathers.
//   TWO 64-thread blocks per ROI (128 channels each), 24 blocks/SM resident.
//   Thread owns contiguous channel pair (2l, 2l+1): each gather is one
//   LDG.32 of __half2 -> warp footprint 128B = ONE line (half of R11).
//   Fixed fully-unrolled 8-load/bin loop; fp32 accumulation; staging +
//   float4 writeback identical to champion.
// ---------------------------------------------------------------------------
#define S2 130

__global__ __launch_bounds__(64, 24) void roialign_kernel(const float* __restrict__ rois,
                                                          float4* __restrict__ out) {
    const int half = blockIdx.x & 1;         // which 128-channel half
    const int n    = blockIdx.x >> 1;        // ROI index
    const int l    = threadIdx.x;            // 0..63

    __shared__ uint4 s_desc[PBIN * SRAT];    // 64 sample descriptors
    __shared__ float s_stage[PBIN * S2];     // [p][128 chans] stride-130 rows

    // ---- Phase A: per-sample descriptors (thread i == sample i) ----
    {
        const float bf    = __ldg(&rois[n * 3 + 0]);
        const float start = __ldg(&rois[n * 3 + 1]);
        const float end   = __ldg(&rois[n * 3 + 2]);
        const float roi_len = fmaxf(end - start, 1.0f);
        const float bin     = roi_len * (1.0f / (float)PBIN);

        const int p = l >> 2;                // bin
        const int s = l & 3;                 // sample
        const float x = start + ((float)p + ((float)s + 0.5f) * 0.25f) * bin;
        const bool valid = (x >= -1.0f) && (x <= (float)TLEN);
        const float xc = fminf(fmaxf(x, 0.0f), (float)(TLEN - 1));
        const int xl = (int)floorf(xc);
        const int xh = min(xl + 1, TLEN - 1);
        const float lx = xc - (float)xl;
        const int b = (int)bf;

        uint4 d;
        d.x = (unsigned)(((b << 9) + xl) << 9);    // byte offset of row xl (512B rows)
        d.y = (unsigned)(((b << 9) + xh) << 9);    // byte offset of row xh
        d.z = __float_as_uint(valid ? (1.0f - lx) * 0.25f : 0.0f);
        d.w = __float_as_uint(valid ? lx * 0.25f : 0.0f);
        s_desc[l] = d;
    }
    __syncthreads();

    // ---- Phase B: one-line fp16 gathers, contiguous channel pair/thread ----
    const char* base = (const char*)g_tr + (half * 128 + 2 * l) * 2;

    #pragma unroll 1
    for (int p = 0; p < PBIN; p++) {
        float a0 = 0.0f, a1 = 0.0f;
        #pragma unroll
        for (int s = 0; s < SRAT; s++) {
            const uint4 d = s_desc[p * SRAT + s];
            const float wlo = __uint_as_float(d.z);
            const float whi = __uint_as_float(d.w);
            const float2 lo = __half22float2(*(const __half2*)(base + d.x));
            const float2 hi = __half22float2(*(const __half2*)(base + d.y));
            a0 += lo.x * wlo + hi.x * whi;   // chan 2l
            a1 += lo.y * wlo + hi.y * whi;   // chan 2l+1
        }
        // STS.64: per half-warp banks cover all 32 exactly once -> conflict-free
        *(float2*)&s_stage[p * S2 + 2 * l] = make_float2(a0, a1);
    }
    __syncthreads();

    // ---- Phase C: coalesced float4 writeback (contiguous half-ROI range) ----
    float4* outn = out + (size_t)n * (CH * PBIN / 4) + half * 512;

    #pragma unroll
    for (int k = 0; k < 8; k++) {
        const int q = l + 64 * k;            // 0..511, coalesced
        const int c = q >> 2;                // channel within half (0..127)
        const int g = q & 3;                 // bin-group
        float4 v;
        v.x = s_stage[(4 * g + 0) * S2 + c];
        v.y = s_stage[(4 * g + 1) * S2 + c];
        v.z = s_stage[(4 * g + 2) * S2 + c];
        v.w = s_stage[(4 * g + 3) * S2 + c];
        outn[q] = v;
    }
}

extern "C" void kernel_launch(void* const* d_in, const int* in_sizes, int n_in,
                              void* d_out, int out_size) {
    const float* input = (const float*)d_in[0];
    const float* rois  = (const float*)d_in[1];
    float4*      out   = (float4*)d_out;

    const int N = in_sizes[1] / 3;       // 2048 ROIs

    dim3 tgrid(TLEN / 32, CH / 32, BS);  // (16, 8, 8)
    dim3 tblk(8, 32);
    transpose_kernel<<<tgrid, tblk>>>(input);

    roialign_kernel<<<N * 2, 64>>>(rois, out);
}

// round 14
// speedup vs baseline: 1.5765x; 1.0286x over previous
#include <cuda_runtime.h>
#include <cuda_fp16.h>

#define BS   8
#define CH   256
#define TLEN 512
#define PBIN 16
#define SRAT 4

// 2 MB transposed-input scratch in FP16: (b, t, c) layout.
__device__ __half2 g_tr[BS * TLEN * CH / 2];

// ---------------------------------------------------------------------------
// Kernel 1: transpose (b, ch, t) fp32 -> (b, t, ch) fp16. 32x32 tiles.
// (identical to the R13 champion)
// ---------------------------------------------------------------------------
__global__ __launch_bounds__(256) void transpose_kernel(const float* __restrict__ in) {
    __shared__ float tile[32][33];
    const int b  = blockIdx.z;
    const int t0 = blockIdx.x * 32;
    const int c0 = blockIdx.y * 32;
    const int tx = threadIdx.x;          // 0..7  (float4 index)
    const int ty = threadIdx.y;          // 0..31

    const float* inb  = in   + (size_t)b * CH * TLEN;
    __half2*     outb = g_tr + (size_t)b * TLEN * (CH / 2);

    const float4 v = *(const float4*)&inb[(size_t)(c0 + ty) * TLEN + (t0 + 4 * tx)];
    tile[ty][4 * tx + 0] = v.x;
    tile[ty][4 * tx + 1] = v.y;
    tile[ty][4 * tx + 2] = v.z;
    tile[ty][4 * tx + 3] = v.w;
    __syncthreads();

    __half2 w2[2];
    w2[0] = __floats2half2_rn(tile[4 * tx + 0][ty], tile[4 * tx + 1][ty]);
    w2[1] = __floats2half2_rn(tile[4 * tx + 2][ty], tile[4 * tx + 3][ty]);
    *(uint2*)&outb[(size_t)(t0 + ty) * (CH / 2) + (c0 / 2 + 2 * tx)] = *(const uint2*)w2;
}

// ---------------------------------------------------------------------------
// Kernel 2: R13 structure + HFMA2 accumulation.
//   TWO 64-thread blocks per ROI (128 channels each), 24 blocks/SM resident.
//   Thread owns channel pair (2l, 2l+1); gather = one LDG.32 of __half2,
//   warp footprint 128B = ONE line. Weights live in the descriptor as
//   broadcast half2 pairs; each bin accumulates via 8 HFMA2 and converts to
//   fp32 ONCE for staging -> ~48% fewer issue slots in the hot loop.
// ---------------------------------------------------------------------------
#define S2 130

__device__ __forceinline__ unsigned h2u(__half2 h) {
    return *reinterpret_cast<unsigned*>(&h);
}

__global__ __launch_bounds__(64, 24) void roialign_kernel(const float* __restrict__ rois,
                                                          float4* __restrict__ out) {
    const int half = blockIdx.x & 1;         // which 128-channel half
    const int n    = blockIdx.x >> 1;        // ROI index
    const int l    = threadIdx.x;            // 0..63

    __shared__ uint4 s_desc[PBIN * SRAT];    // 64 sample descriptors
    __shared__ float s_stage[PBIN * S2];     // [p][128 chans] stride-130 rows

    // ---- Phase A: per-sample descriptors (thread i == sample i) ----
    {
        const float bf    = __ldg(&rois[n * 3 + 0]);
        const float start = __ldg(&rois[n * 3 + 1]);
        const float end   = __ldg(&rois[n * 3 + 2]);
        const float roi_len = fmaxf(end - start, 1.0f);
        const float bin     = roi_len * (1.0f / (float)PBIN);

        const int p = l >> 2;                // bin
        const int s = l & 3;                 // sample
        const float x = start + ((float)p + ((float)s + 0.5f) * 0.25f) * bin;
        const bool valid = (x >= -1.0f) && (x <= (float)TLEN);
        const float xc = fminf(fmaxf(x, 0.0f), (float)(TLEN - 1));
        const int xl = (int)floorf(xc);
        const int xh = min(xl + 1, TLEN - 1);
        const float lx = xc - (float)xl;
        const int b = (int)bf;

        const float wlo = valid ? (1.0f - lx) * 0.25f : 0.0f;
        const float whi = valid ? lx * 0.25f : 0.0f;

        uint4 d;
        d.x = (unsigned)(((b << 9) + xl) << 9);    // byte offset of row xl (512B rows)
        d.y = (unsigned)(((b << 9) + xh) << 9);    // byte offset of row xh
        d.z = h2u(__float2half2_rn(wlo));          // (wlo, wlo) fp16
        d.w = h2u(__float2half2_rn(whi));          // (whi, whi) fp16
        s_desc[l] = d;
    }
    __syncthreads();

    // ---- Phase B: one-line fp16 gathers + HFMA2 bin accumulation ----
    const char* base = (const char*)g_tr + (half * 128 + 2 * l) * 2;

    #pragma unroll 1
    for (int p = 0; p < PBIN; p++) {
        __half2 acc = __float2half2_rn(0.0f);
        #pragma unroll
        for (int s = 0; s < SRAT; s++) {
            const uint4 d = s_desc[p * SRAT + s];
            const __half2 wlo2 = *reinterpret_cast<const __half2*>(&d.z);
            const __half2 whi2 = *reinterpret_cast<const __half2*>(&d.w);
            const __half2 lo = *(const __half2*)(base + d.x);
            const __half2 hi = *(const __half2*)(base + d.y);
            acc = __hfma2(lo, wlo2, acc);
            acc = __hfma2(hi, whi2, acc);
        }
        const float2 a = __half22float2(acc);      // one convert per bin
        // STS.64: per half-warp banks cover all 32 exactly once -> conflict-free
        *(float2*)&s_stage[p * S2 + 2 * l] = a;
    }
    __syncthreads();

    // ---- Phase C: coalesced float4 writeback (contiguous half-ROI range) ----
    float4* outn = out + (size_t)n * (CH * PBIN / 4) + half * 512;

    #pragma unroll
    for (int k = 0; k < 8; k++) {
        const int q = l + 64 * k;            // 0..511, coalesced
        const int c = q >> 2;                // channel within half (0..127)
        const int g = q & 3;                 // bin-group
        float4 v;
        v.x = s_stage[(4 * g + 0) * S2 + c];
        v.y = s_stage[(4 * g + 1) * S2 + c];
        v.z = s_stage[(4 * g + 2) * S2 + c];
        v.w = s_stage[(4 * g + 3) * S2 + c];
        outn[q] = v;
    }
}

extern "C" void kernel_launch(void* const* d_in, const int* in_sizes, int n_in,
                              void* d_out, int out_size) {
    const float* input = (const float*)d_in[0];
    const float* rois  = (const float*)d_in[1];
    float4*      out   = (float4*)d_out;

    const int N = in_sizes[1] / 3;       // 2048 ROIs

    dim3 tgrid(TLEN / 32, CH / 32, BS);  // (16, 8, 8)
    dim3 tblk(8, 32);
    transpose_kernel<<<tgrid, tblk>>>(input);

    roialign_kernel<<<N * 2, 64>>>(rois, out);
}

// round 15
// speedup vs baseline: 1.6621x; 1.0543x over previous
#include <cuda_runtime.h>
#include <cuda_fp16.h>

#define BS   8
#define CH   256
#define TLEN 512
#define PBIN 16
#define SRAT 4

// 2 MB transposed-input scratch in FP16 (b, t, c) + one zero pad row so the
// unconditional hi = lo + 512B load is safe at xl = 511 of the last batch
// (whi = 0 there, and device globals are zero-initialized).
__device__ __half2 g_tr[BS * TLEN * CH / 2 + CH / 2];

// ---------------------------------------------------------------------------
// Kernel 1: transpose (b, ch, t) fp32 -> (b, t, ch) fp16. 32x32 tiles.
// ---------------------------------------------------------------------------
__global__ __launch_bounds__(256) void transpose_kernel(const float* __restrict__ in) {
    __shared__ float tile[32][33];
    const int b  = blockIdx.z;
    const int t0 = blockIdx.x * 32;
    const int c0 = blockIdx.y * 32;
    const int tx = threadIdx.x;          // 0..7  (float4 index)
    const int ty = threadIdx.y;          // 0..31

    const float* inb  = in   + (size_t)b * CH * TLEN;
    __half2*     outb = g_tr + (size_t)b * TLEN * (CH / 2);

    const float4 v = *(const float4*)&inb[(size_t)(c0 + ty) * TLEN + (t0 + 4 * tx)];
    tile[ty][4 * tx + 0] = v.x;
    tile[ty][4 * tx + 1] = v.y;
    tile[ty][4 * tx + 2] = v.z;
    tile[ty][4 * tx + 3] = v.w;
    __syncthreads();

    __half2 w2[2];
    w2[0] = __floats2half2_rn(tile[4 * tx + 0][ty], tile[4 * tx + 1][ty]);
    w2[1] = __floats2half2_rn(tile[4 * tx + 2][ty], tile[4 * tx + 3][ty]);
    *(uint2*)&outb[(size_t)(t0 + ty) * (CH / 2) + (c0 / 2 + 2 * tx)] = *(const uint2*)w2;
}

// ---------------------------------------------------------------------------
// Kernel 2: fp16 gathers + HFMA2, compact uint2 descriptors, unroll-2 bins.
//   TWO 64-thread blocks per ROI (128 channels each). Thread owns channel
//   pair (2l, 2l+1); each sample needs ONE address (hi row is lo + 512B
//   immediate). 16 one-line LDG in flight per thread at 20 blocks/SM.
// ---------------------------------------------------------------------------
#define S2 130

__device__ __forceinline__ unsigned h2u(__half2 h) {
    return *reinterpret_cast<unsigned*>(&h);
}
__device__ __forceinline__ __half2 u2h(unsigned u) {
    return *reinterpret_cast<__half2*>(&u);
}

__global__ __launch_bounds__(64, 20) void roialign_kernel(const float* __restrict__ rois,
                                                          float4* __restrict__ out) {
    const int half = blockIdx.x & 1;         // which 128-channel half
    const int n    = blockIdx.x >> 1;        // ROI index
    const int l    = threadIdx.x;            // 0..63

    __shared__ uint2 s_desc[PBIN * SRAT];    // (row-offset, packed (wlo,whi))
    __shared__ float s_stage[PBIN * S2];     // [p][128 chans] stride-130 rows

    // ---- Phase A: per-sample descriptors (thread i == sample i) ----
    {
        const float bf    = __ldg(&rois[n * 3 + 0]);
        const float start = __ldg(&rois[n * 3 + 1]);
        const float end   = __ldg(&rois[n * 3 + 2]);
        const float roi_len = fmaxf(end - start, 1.0f);
        const float bin     = roi_len * (1.0f / (float)PBIN);

        const int p = l >> 2;                // bin
        const int s = l & 3;                 // sample
        const float x = start + ((float)p + ((float)s + 0.5f) * 0.25f) * bin;
        const bool valid = (x >= -1.0f) && (x <= (float)TLEN);
        const float xc = fminf(fmaxf(x, 0.0f), (float)(TLEN - 1));
        const int xl = (int)floorf(xc);
        const float lx = xc - (float)xl;     // lx = 0 when xl = 511 -> whi = 0
        const int b = (int)bf;

        const float wlo = valid ? (1.0f - lx) * 0.25f : 0.0f;
        const float whi = valid ? lx * 0.25f : 0.0f;

        uint2 d;
        d.x = (unsigned)(((b << 9) + xl) << 9);        // byte offset of row xl
        d.y = h2u(__floats2half2_rn(wlo, whi));        // packed weights
        s_desc[l] = d;
    }
    __syncthreads();

    // ---- Phase B: one-line fp16 gathers, hi row = +512B immediate ----
    const char* base = (const char*)g_tr + (half * 128 + 2 * l) * 2;

    #pragma unroll 2
    for (int p = 0; p < PBIN; p++) {
        __half2 acc = __float2half2_rn(0.0f);
        #pragma unroll
        for (int s = 0; s < SRAT; s++) {
            const uint2 d = s_desc[p * SRAT + s];
            const char* a = base + d.x;
            const __half2 lo = *(const __half2*)(a);
            const __half2 hi = *(const __half2*)(a + 512);
            const __half2 w  = u2h(d.y);
            acc = __hfma2(lo, __low2half2(w), acc);
            acc = __hfma2(hi, __high2half2(w), acc);
        }
        const float2 a2 = __half22float2(acc);     // one convert per bin
        // STS.64: per half-warp banks cover all 32 exactly once -> conflict-free
        *(float2*)&s_stage[p * S2 + 2 * l] = a2;
    }
    __syncthreads();

    // ---- Phase C: coalesced float4 writeback (contiguous half-ROI range) ----
    float4* outn = out + (size_t)n * (CH * PBIN / 4) + half * 512;

    #pragma unroll
    for (int k = 0; k < 8; k++) {
        const int q = l + 64 * k;            // 0..511, coalesced
        const int c = q >> 2;                // channel within half (0..127)
        const int g = q & 3;                 // bin-group
        float4 v;
        v.x = s_stage[(4 * g + 0) * S2 + c];
        v.y = s_stage[(4 * g + 1) * S2 + c];
        v.z = s_stage[(4 * g + 2) * S2 + c];
        v.w = s_stage[(4 * g + 3) * S2 + c];
        outn[q] = v;
    }
}

extern "C" void kernel_launch(void* const* d_in, const int* in_sizes, int n_in,
                              void* d_out, int out_size) {
    const float* input = (const float*)d_in[0];
    const float* rois  = (const float*)d_in[1];
    float4*      out   = (float4*)d_out;

    const int N = in_sizes[1] / 3;       // 2048 ROIs

    dim3 tgrid(TLEN / 32, CH / 32, BS);  // (16, 8, 8)
    dim3 tblk(8, 32);
    transpose_kernel<<<tgrid, tblk>>>(input);

    roialign_kernel<<<N * 2, 64>>>(rois, out);
}

// round 16
// speedup vs baseline: 1.8615x; 1.1199x over previous
#include <cuda_runtime.h>
#include <cuda_fp16.h>

#define BS   8
#define CH   256
#define TLEN 512
#define PBIN 16
#define SRAT 4

// 2 MB transposed-input scratch in FP16 (b, t, c) + one zero pad row so the
// unconditional hi = lo + 512B load is safe at xl = 511 of the last batch
// (whi = 0 there, and device globals are zero-initialized).
__device__ __half2 g_tr[BS * TLEN * CH / 2 + CH / 2];

// ---------------------------------------------------------------------------
// Kernel 1: transpose (b, ch, t) fp32 -> (b, t, ch) fp16. 32x32 tiles.
// ---------------------------------------------------------------------------
__global__ __launch_bounds__(256) void transpose_kernel(const float* __restrict__ in) {
    __shared__ float tile[32][33];
    const int b  = blockIdx.z;
    const int t0 = blockIdx.x * 32;
    const int c0 = blockIdx.y * 32;
    const int tx = threadIdx.x;          // 0..7  (float4 index)
    const int ty = threadIdx.y;          // 0..31

    const float* inb  = in   + (size_t)b * CH * TLEN;
    __half2*     outb = g_tr + (size_t)b * TLEN * (CH / 2);

    const float4 v = *(const float4*)&inb[(size_t)(c0 + ty) * TLEN + (t0 + 4 * tx)];
    tile[ty][4 * tx + 0] = v.x;
    tile[ty][4 * tx + 1] = v.y;
    tile[ty][4 * tx + 2] = v.z;
    tile[ty][4 * tx + 3] = v.w;
    __syncthreads();

    __half2 w2[2];
    w2[0] = __floats2half2_rn(tile[4 * tx + 0][ty], tile[4 * tx + 1][ty]);
    w2[1] = __floats2half2_rn(tile[4 * tx + 2][ty], tile[4 * tx + 3][ty]);
    *(uint2*)&outb[(size_t)(t0 + ty) * (CH / 2) + (c0 / 2 + 2 * tx)] = *(const uint2*)w2;
}

// ---------------------------------------------------------------------------
// Kernel 2: fp16 gathers + HFMA2, uint2 descriptors, UNROLL-4 bins.
//   TWO 64-thread blocks per ROI (128 channels each). Thread owns channel
//   pair (2l, 2l+1); one address per sample (hi row = +512B immediate).
//   32 one-line LDG in flight per thread; __launch_bounds__(64,18) keeps
//   36 warps/SM resident. Staging kept in half2 (no extra precision loss,
//   acc is fp16): STS.32 conflict-free, convert to fp32 in the writeback.
// ---------------------------------------------------------------------------
#define S2H 132   // half2 stage row stride (channel pairs + skew)

__device__ __forceinline__ unsigned h2u(__half2 h) {
    return *reinterpret_cast<unsigned*>(&h);
}
__device__ __forceinline__ __half2 u2h(unsigned u) {
    return *reinterpret_cast<__half2*>(&u);
}

__global__ __launch_bounds__(64, 18) void roialign_kernel(const float* __restrict__ rois,
                                                          float4* __restrict__ out) {
    const int half = blockIdx.x & 1;         // which 128-channel half
    const int n    = blockIdx.x >> 1;        // ROI index
    const int l    = threadIdx.x;            // 0..63

    __shared__ uint2   s_desc[PBIN * SRAT];  // (row-offset, packed (wlo,whi))
    __shared__ __half2 s_stage[PBIN * S2H];  // [p][64 chan-pairs] skewed rows

    // ---- Phase A: per-sample descriptors (thread i == sample i) ----
    {
        const float bf    = __ldg(&rois[n * 3 + 0]);
        const float start = __ldg(&rois[n * 3 + 1]);
        const float end   = __ldg(&rois[n * 3 + 2]);
        const float roi_len = fmaxf(end - start, 1.0f);
        const float bin     = roi_len * (1.0f / (float)PBIN);

        const int p = l >> 2;                // bin
        const int s = l & 3;                 // sample
        const float x = start + ((float)p + ((float)s + 0.5f) * 0.25f) * bin;
        const bool valid = (x >= -1.0f) && (x <= (float)TLEN);
        const float xc = fminf(fmaxf(x, 0.0f), (float)(TLEN - 1));
        const int xl = (int)floorf(xc);
        const float lx = xc - (float)xl;     // lx = 0 when xl = 511 -> whi = 0
        const int b = (int)bf;

        const float wlo = valid ? (1.0f - lx) * 0.25f : 0.0f;
        const float whi = valid ? lx * 0.25f : 0.0f;

        uint2 d;
        d.x = (unsigned)(((b << 9) + xl) << 9);        // byte offset of row xl
        d.y = h2u(__floats2half2_rn(wlo, whi));        // packed weights
        s_desc[l] = d;
    }
    __syncthreads();

    // ---- Phase B: one-line fp16 gathers, 4 bins per iteration ----
    const char* base = (const char*)g_tr + (half * 128 + 2 * l) * 2;

    #pragma unroll 4
    for (int p = 0; p < PBIN; p++) {
        __half2 acc = __float2half2_rn(0.0f);
        #pragma unroll
        for (int s = 0; s < SRAT; s++) {
            const uint2 d = s_desc[p * SRAT + s];
            const char* a = base + d.x;
            const __half2 lo = *(const __half2*)(a);
            const __half2 hi = *(const __half2*)(a + 512);
            const __half2 w  = u2h(d.y);
            acc = __hfma2(lo, __low2half2(w), acc);
            acc = __hfma2(hi, __high2half2(w), acc);
        }
        // STS.32: 64 threads x 4B span 256B; each half-warp covers 16 distinct
        // banks (2-word granularity) with no overlap -> conflict-free.
        s_stage[p * S2H + l] = acc;
    }
    __syncthreads();

    // ---- Phase C: coalesced float4 writeback (contiguous half-ROI range) ----
    float4* outn = out + (size_t)n * (CH * PBIN / 4) + half * 512;

    #pragma unroll
    for (int k = 0; k < 8; k++) {
        const int q = l + 64 * k;            // 0..511, coalesced
        const int cp = q >> 3;               // channel pair (0..63)
        const int g  = q & 3;                // bin-group
        const int hl = (q >> 2) & 1;         // low/high half of the pair
        float4 v;
        #pragma unroll
        for (int j = 0; j < 4; j++) {
            const float2 f2 = __half22float2(s_stage[(4 * g + j) * S2H + cp]);
            ((float*)&v)[j] = hl ? f2.y : f2.x;
        }
        // out element index: c*16 + p with c = 2cp + hl, p = 4g + j
        outn[(2 * cp + hl) * 4 + g] = v;
    }
}

extern "C" void kernel_launch(void* const* d_in, const int* in_sizes, int n_in,
                              void* d_out, int out_size) {
    const float* input = (const float*)d_in[0];
    const float* rois  = (const float*)d_in[1];
    float4*      out   = (float4*)d_out;

    const int N = in_sizes[1] / 3;       // 2048 ROIs

    dim3 tgrid(TLEN / 32, CH / 32, BS);  // (16, 8, 8)
    dim3 tblk(8, 32);
    transpose_kernel<<<tgrid, tblk>>>(input);

    roialign_kernel<<<N * 2, 64>>>(rois, out);
}